// round 15
// baseline (speedup 1.0000x reference)
#include <cuda_runtime.h>
#include <cuda_fp16.h>
#include <math.h>
#include <stdint.h>

#define N_ROWS_MAX 100000
#define D 64
#define NGH 16
#define NSC 10
#define EPSF 1e-10f
#define FULL 0xFFFFFFFFu

#define WPB 8           // warps per block
#define RPW 16          // rows per warp
#define RPB 128         // rows per block

#define ASTRIDE 136     // A-tile row stride in halfs (272B) — conflict-free

typedef unsigned long long ull;

// ---- scratch (device globals per allocation rules) ----
__device__ __half2 g_rs_h[(size_t)N_ROWS_MAX * 32];  // rs/(||rs||^2+eps) fp16
__device__ float2  g_ss[N_ROWS_MAX];                 // (scale = sq+eps, selfsim)
__device__ uint2   g_Bfrag[64 * 32];                 // [kstep*8+ntile][lane]

// ---- packed f32x2 helpers ----
__device__ __forceinline__ ull pk2(float x, float y) {
    ull r; asm("mov.b64 %0, {%1, %2};" : "=l"(r) : "f"(x), "f"(y)); return r;
}
__device__ __forceinline__ float2 upk2(ull v) {
    float2 r; asm("mov.b64 {%0, %1}, %2;" : "=f"(r.x), "=f"(r.y) : "l"(v)); return r;
}
__device__ __forceinline__ void fma2(ull& d, ull a, ull b, ull c) {
    asm("fma.rn.f32x2 %0, %1, %2, %3;" : "=l"(d) : "l"(a), "l"(b), "l"(c));
}
__device__ __forceinline__ float2 h2f(unsigned int h) {
    return __half22float2(*reinterpret_cast<__half2*>(&h));
}

// ---------------------------------------------------------------------------
// Kernel A: per-row scene sums -> fp16 normalized table + (scale, selfsim);
// also builds per-lane HMMA B fragments of agg_W.
// ---------------------------------------------------------------------------
__global__ void rowsum_kernel(const float* __restrict__ scene_emb,
                              const int* __restrict__ cate_scene_pad,
                              const float* __restrict__ agg_W,
                              int n_rows) {
    int gtid = blockIdx.x * blockDim.x + threadIdx.x;

    // B-fragment build: first 2048 threads, one uint2 each.
    if (gtid < 64 * 32) {
        int lane  = gtid & 31;
        int tile  = gtid >> 5;
        int kstep = tile >> 3;
        int ntile = tile & 7;
        int tid4  = lane & 3;
        int gid   = lane >> 2;
        int k0 = kstep * 16 + tid4 * 2;
        int n  = ntile * 8 + gid;
        __half2 r0 = __floats2half2_rn(agg_W[n * 128 + k0],     agg_W[n * 128 + k0 + 1]);
        __half2 r1 = __floats2half2_rn(agg_W[n * 128 + k0 + 8], agg_W[n * 128 + k0 + 9]);
        uint2 u;
        u.x = *reinterpret_cast<unsigned int*>(&r0);
        u.y = *reinterpret_cast<unsigned int*>(&r1);
        g_Bfrag[tile * 32 + lane] = u;
    }

    int row = gtid >> 4;
    int sub = gtid & 15;
    if (row >= n_rows) return;
    int lane = threadIdx.x & 31;
    int group_base = lane & 16;

    int myidx = 0;
    if (sub < NSC) myidx = __ldg(cate_scene_pad + (size_t)row * NSC + sub);

    float4 acc = make_float4(0.f, 0.f, 0.f, 0.f);
#pragma unroll
    for (int k = 0; k < NSC; k++) {
        int j = __shfl_sync(FULL, myidx, group_base + k);
        float4 v = ((const float4*)(scene_emb + (size_t)j * D))[sub];
        acc.x += v.x; acc.y += v.y; acc.z += v.z; acc.w += v.w;
    }

    float sq = acc.x * acc.x + acc.y * acc.y + acc.z * acc.z + acc.w * acc.w;
#pragma unroll
    for (int o = 8; o >= 1; o >>= 1)
        sq += __shfl_xor_sync(FULL, sq, o);

    float scale = sq + EPSF;
    float inv = 1.0f / scale;

    __half2 h0 = __floats2half2_rn(acc.x * inv, acc.y * inv);
    __half2 h1 = __floats2half2_rn(acc.z * inv, acc.w * inv);
    uint2 u;
    u.x = *reinterpret_cast<unsigned int*>(&h0);
    u.y = *reinterpret_cast<unsigned int*>(&h1);
    ((uint2*)g_rs_h)[(size_t)row * 16 + sub] = u;

    if (sub == 0) g_ss[row] = make_float2(scale, sq * inv * inv);
}

// Butterfly merge at xor-offset o.
__device__ __forceinline__ float bmerge(float a, float b, int o, int lane) {
    float x = (lane & o) ? b : a;
    float y = (lane & o) ? a : b;
    y = __shfl_xor_sync(FULL, y, o);
    return x + y;
}

__device__ __forceinline__ void mma16816(float* c, uint32_t a0, uint32_t a1,
                                         uint32_t a2, uint32_t a3,
                                         uint32_t b0, uint32_t b1) {
    asm volatile(
        "mma.sync.aligned.m16n8k16.row.col.f32.f16.f16.f32 "
        "{%0,%1,%2,%3}, {%4,%5,%6,%7}, {%8,%9}, {%0,%1,%2,%3};"
        : "+f"(c[0]), "+f"(c[1]), "+f"(c[2]), "+f"(c[3])
        : "r"(a0), "r"(a1), "r"(a2), "r"(a3), "r"(b0), "r"(b1));
}

// fp16 row (16B/lane) dot fp32 self fragments
__device__ __forceinline__ float dot8(uint4 u, float2 s0, float2 s1,
                                      float2 s2, float2 s3) {
    float2 f0 = h2f(u.x), f1 = h2f(u.y), f2 = h2f(u.z), f3 = h2f(u.w);
    float d = f0.x * s0.x;
    d = fmaf(f0.y, s0.y, d);
    d = fmaf(f1.x, s1.x, d);
    d = fmaf(f1.y, s1.y, d);
    d = fmaf(f2.x, s2.x, d);
    d = fmaf(f2.y, s2.y, d);
    d = fmaf(f3.x, s3.x, d);
    d = fmaf(f3.y, s3.y, d);
    return d;
}

// ---------------------------------------------------------------------------
// Kernel B: each warp owns 16 rows end-to-end.
//   Phase 1: QUARTER-warp rows — 4 rows per iteration, 8 lanes/row, 16B/lane.
//            Each lane owns neighbors 2s,2s+1 (int2). 8-lane butterfly leaves
//            lane s holding dots for exactly those neighbors (mask local).
//   Phase 2: 64x HMMA m16n8k16 -> out[16][64] per warp; bias+ELU; direct STG.
// ---------------------------------------------------------------------------
__global__ void __launch_bounds__(256, 4)
main_kernel(const float* __restrict__ cate_emb,
            const int* __restrict__ c_cate_pad,
            const float* __restrict__ agg_b,
            float* __restrict__ out,
            int n_rows, int v_cates) {
    __shared__ __half sA[RPB * ASTRIDE];   // 128 rows x 136 halfs (pad 8)

    int tid  = threadIdx.x;
    int warp = tid >> 5;
    int lane = tid & 31;

    int rowbase = blockIdx.x * RPB + warp * RPW;
    int q     = lane >> 3;       // quarter = row within group of 4
    int s     = lane & 7;        // lane within quarter
    int qbase = lane & 24;       // shuffle base of this quarter

    // ---- batched neighbor-index prefetch (each lane: neighbors 2s, 2s+1) ----
    int2 nid[4];
#pragma unroll
    for (int rp = 0; rp < 4; rp++) {
        int row  = rowbase + 4 * rp + q;
        int vrow = row < n_rows ? row : n_rows - 1;
        nid[rp] = __ldg((const int2*)(c_cate_pad + (size_t)vrow * NGH) + s);
    }

    // ---- Phase 1: attention, 4 rows per iteration ----
#pragma unroll 1
    for (int rp = 0; rp < 4; rp++) {
        int row  = rowbase + 4 * rp + q;
        int vrow = row < n_rows ? row : n_rows - 1;
        int2 nd = nid[rp];

        uint4 us = __ldg((const uint4*)g_rs_h + (size_t)vrow * 8 + s);
        float2 ss = g_ss[vrow];                 // (scale, selfsim)
        float2 sf0 = h2f(us.x), sf1 = h2f(us.y), sf2 = h2f(us.z), sf3 = h2f(us.w);

        // 16 neighbor dot partials (LDG.128 gathers, 2 per jj)
        float dtp[16];
#pragma unroll
        for (int jj = 0; jj < 8; jj++) {
            int px = __shfl_sync(FULL, nd.x, qbase + jj);
            int py = __shfl_sync(FULL, nd.y, qbase + jj);
            uint4 ux = __ldg((const uint4*)g_rs_h + (size_t)px * 8 + s);
            uint4 uy = __ldg((const uint4*)g_rs_h + (size_t)py * 8 + s);
            dtp[2 * jj]     = dot8(ux, sf0, sf1, sf2, sf3);
            dtp[2 * jj + 1] = dot8(uy, sf0, sf1, sf2, sf3);
        }

        // 8-lane butterfly: lane s ends with dots for neighbors 2s, 2s+1
#pragma unroll
        for (int i = 0; i < 8; i++) dtp[i] = bmerge(dtp[i], dtp[i + 8], 4, lane);
#pragma unroll
        for (int i = 0; i < 4; i++) dtp[i] = bmerge(dtp[i], dtp[i + 4], 2, lane);
#pragma unroll
        for (int i = 0; i < 2; i++) dtp[i] = bmerge(dtp[i], dtp[i + 2], 1, lane);

        float miu0 = (nd.x < v_cates - 1) ? __expf(dtp[0]) : 0.f;
        float miu1 = (nd.y < v_cates - 1) ? __expf(dtp[1]) : 0.f;

        // denom over the quarter
        float dv = miu0 + miu1;
#pragma unroll
        for (int o = 4; o >= 1; o >>= 1)
            dv += __shfl_xor_sync(FULL, dv, o);

        float miu_self = (vrow < v_cates - 1) ? __expf(ss.y) : 0.f;
        float rden = 1.0f / (dv + miu_self + EPSF);

        // aggregation: lane covers output floats e = 8s..8s+7 (4 ull chains)
        const ulonglong2* cerow = (const ulonglong2*)(cate_emb + (size_t)vrow * D);
        ulonglong2 cs0 = __ldg(cerow + 2 * s);
        ulonglong2 cs1 = __ldg(cerow + 2 * s + 1);
        ull msd = pk2(miu_self, miu_self);
        ull A0, A1, A2, A3;
        fma2(A0, msd, cs0.x, pk2(0.f, 0.f));
        fma2(A1, msd, cs0.y, pk2(0.f, 0.f));
        fma2(A2, msd, cs1.x, pk2(0.f, 0.f));
        fma2(A3, msd, cs1.y, pk2(0.f, 0.f));
#pragma unroll
        for (int jj = 0; jj < 8; jj++) {
            float m0 = __shfl_sync(FULL, miu0, qbase + jj);
            float m1 = __shfl_sync(FULL, miu1, qbase + jj);
            int   px = __shfl_sync(FULL, nd.x, qbase + jj);
            int   py = __shfl_sync(FULL, nd.y, qbase + jj);
            const ulonglong2* cx = (const ulonglong2*)(cate_emb + (size_t)px * D);
            const ulonglong2* cy = (const ulonglong2*)(cate_emb + (size_t)py * D);
            ulonglong2 cv0 = __ldg(cx + 2 * s);
            ulonglong2 cv1 = __ldg(cx + 2 * s + 1);
            ulonglong2 cw0 = __ldg(cy + 2 * s);
            ulonglong2 cw1 = __ldg(cy + 2 * s + 1);
            ull mm0 = pk2(m0, m0);
            ull mm1 = pk2(m1, m1);
            fma2(A0, mm0, cv0.x, A0);
            fma2(A1, mm0, cv0.y, A1);
            fma2(A2, mm0, cv1.x, A2);
            fma2(A3, mm0, cv1.y, A3);
            fma2(A0, mm1, cw0.x, A0);
            fma2(A1, mm1, cw0.y, A1);
            fma2(A2, mm1, cw1.x, A2);
            fma2(A3, mm1, cw1.y, A3);
        }
        float2 g0 = upk2(A0), g1 = upk2(A1), g2 = upk2(A2), g3 = upk2(A3);

        // h store (fp16): rs at e=8s.., agg at e=64+8s.. — STS.128, conflict-free
        int rt = warp * RPW + 4 * rp + q;
        __half* hrow = sA + rt * ASTRIDE;
        float sc = ss.x;
        __half2 r0 = __floats2half2_rn(sf0.x * sc, sf0.y * sc);
        __half2 r1 = __floats2half2_rn(sf1.x * sc, sf1.y * sc);
        __half2 r2 = __floats2half2_rn(sf2.x * sc, sf2.y * sc);
        __half2 r3 = __floats2half2_rn(sf3.x * sc, sf3.y * sc);
        uint4 w0;
        w0.x = *reinterpret_cast<unsigned int*>(&r0);
        w0.y = *reinterpret_cast<unsigned int*>(&r1);
        w0.z = *reinterpret_cast<unsigned int*>(&r2);
        w0.w = *reinterpret_cast<unsigned int*>(&r3);
        *(uint4*)(hrow + 8 * s) = w0;

        __half2 a0 = __floats2half2_rn(g0.x * rden, g0.y * rden);
        __half2 a1 = __floats2half2_rn(g1.x * rden, g1.y * rden);
        __half2 a2 = __floats2half2_rn(g2.x * rden, g2.y * rden);
        __half2 a3 = __floats2half2_rn(g3.x * rden, g3.y * rden);
        uint4 w1;
        w1.x = *reinterpret_cast<unsigned int*>(&a0);
        w1.y = *reinterpret_cast<unsigned int*>(&a1);
        w1.z = *reinterpret_cast<unsigned int*>(&a2);
        w1.w = *reinterpret_cast<unsigned int*>(&a3);
        *(uint4*)(hrow + 64 + 8 * s) = w1;
    }
    __syncwarp();

    // ---- Phase 2: HMMA matvec, 16 rows x 64 cols per warp ----
    int gid  = lane >> 2;      // 0..7
    int tid4 = lane & 3;       // 0..3

    float acc[8][4];
#pragma unroll
    for (int n = 0; n < 8; n++)
#pragma unroll
        for (int i = 0; i < 4; i++) acc[n][i] = 0.f;

    const __half* a_base0 = sA + (warp * RPW + gid) * ASTRIDE + tid4 * 2;
    const __half* a_base1 = a_base0 + 8 * ASTRIDE;

#pragma unroll
    for (int k = 0; k < 8; k++) {
        uint32_t a0 = *(const uint32_t*)(a_base0 + k * 16);
        uint32_t a1 = *(const uint32_t*)(a_base1 + k * 16);
        uint32_t a2 = *(const uint32_t*)(a_base0 + k * 16 + 8);
        uint32_t a3 = *(const uint32_t*)(a_base1 + k * 16 + 8);
#pragma unroll
        for (int n = 0; n < 8; n++) {
            uint2 bf = __ldg(&g_Bfrag[(k * 8 + n) * 32 + lane]);
            mma16816(acc[n], a0, a1, a2, a3, bf.x, bf.y);
        }
    }

    // ---- epilogue: bias + ELU + direct stores ----
    int grow0 = rowbase + gid;
    int grow1 = grow0 + 8;
#pragma unroll
    for (int n = 0; n < 8; n++) {
        int col = n * 8 + tid4 * 2;
        float2 bb = *(const float2*)(agg_b + col);
        if (grow0 < n_rows) {
            float v0 = acc[n][0] + bb.x;
            float v1 = acc[n][1] + bb.y;
            v0 = v0 > 0.f ? v0 : expm1f(v0);
            v1 = v1 > 0.f ? v1 : expm1f(v1);
            *(float2*)(out + (size_t)grow0 * D + col) = make_float2(v0, v1);
        }
        if (grow1 < n_rows) {
            float v2 = acc[n][2] + bb.x;
            float v3 = acc[n][3] + bb.y;
            v2 = v2 > 0.f ? v2 : expm1f(v2);
            v3 = v3 > 0.f ? v3 : expm1f(v3);
            *(float2*)(out + (size_t)grow1 * D + col) = make_float2(v2, v3);
        }
    }
}

// ---------------------------------------------------------------------------
// Inputs (metadata order):
//  0 cids, 1 cate_emb_w [Vc,64], 2 scene_emb_w [Vs,64], 3 cate_scene_pad [N,10],
//  4 c_cate_pad [N,16], 5 agg_W [64,128], 6 agg_b [64]   -> out f32 [N,64]
// ---------------------------------------------------------------------------
extern "C" void kernel_launch(void* const* d_in, const int* in_sizes, int n_in,
                              void* d_out, int out_size) {
    const float* cate_emb       = (const float*)d_in[1];
    const float* scene_emb      = (const float*)d_in[2];
    const int*   cate_scene_pad = (const int*)d_in[3];
    const int*   c_cate_pad     = (const int*)d_in[4];
    const float* agg_W          = (const float*)d_in[5];
    const float* agg_b          = (const float*)d_in[6];
    float* out = (float*)d_out;

    int n_rows  = in_sizes[4] / NGH;   // 100000
    int v_cates = in_sizes[1] / D;     // 100000

    int threadsA = 256;
    int blocksA = (n_rows * 16 + threadsA - 1) / threadsA;
    rowsum_kernel<<<blocksA, threadsA>>>(scene_emb, cate_scene_pad, agg_W, n_rows);

    int blocksB = (n_rows + RPB - 1) / RPB;
    main_kernel<<<blocksB, 256>>>(cate_emb, c_cate_pad, agg_b,
                                  out, n_rows, v_cates);
}

// round 16
// speedup vs baseline: 1.1550x; 1.1550x over previous
#include <cuda_runtime.h>
#include <cuda_fp16.h>
#include <math.h>
#include <stdint.h>

#define N_ROWS_MAX 100000
#define D 64
#define NGH 16
#define NSC 10
#define EPSF 1e-10f
#define FULL 0xFFFFFFFFu

#define WPB 8           // warps per block
#define RPW 16          // rows per warp
#define RPB 128         // rows per block

#define ASTRIDE 136     // A-tile row stride in halfs (272B) — conflict-free

typedef unsigned long long ull;

// ---- scratch (device globals per allocation rules) ----
__device__ __half2 g_rs_h[(size_t)N_ROWS_MAX * 32];  // rs/(||rs||^2+eps) fp16
__device__ uint4   g_ce_h[(size_t)N_ROWS_MAX * 8];   // cate_emb fp16 shadow (128B/row)
__device__ float2  g_ss[N_ROWS_MAX];                 // (scale = sq+eps, selfsim)
__device__ uint2   g_Bfrag[64 * 32];                 // [kstep*8+ntile][lane]

// ---- packed f32x2 helpers ----
__device__ __forceinline__ ull pk2(float x, float y) {
    ull r; asm("mov.b64 %0, {%1, %2};" : "=l"(r) : "f"(x), "f"(y)); return r;
}
__device__ __forceinline__ float2 upk2(ull v) {
    float2 r; asm("mov.b64 {%0, %1}, %2;" : "=f"(r.x), "=f"(r.y) : "l"(v)); return r;
}
__device__ __forceinline__ void fma2(ull& d, ull a, ull b, ull c) {
    asm("fma.rn.f32x2 %0, %1, %2, %3;" : "=l"(d) : "l"(a), "l"(b), "l"(c));
}
__device__ __forceinline__ float2 h2f(unsigned int h) {
    return __half22float2(*reinterpret_cast<__half2*>(&h));
}
// fp16x2 word -> packed f32x2 register pair
__device__ __forceinline__ ull h2p(unsigned int h) {
    float2 f = h2f(h);
    return pk2(f.x, f.y);
}

// ---------------------------------------------------------------------------
// Kernel A: per-row scene sums -> fp16 normalized table + (scale, selfsim);
// builds HMMA B fragments of agg_W and the fp16 cate_emb shadow.
// ---------------------------------------------------------------------------
__global__ void rowsum_kernel(const float* __restrict__ scene_emb,
                              const int* __restrict__ cate_scene_pad,
                              const float* __restrict__ agg_W,
                              const float* __restrict__ cate_emb,
                              int n_rows, int v_cates) {
    int gtid = blockIdx.x * blockDim.x + threadIdx.x;

    // B-fragment build: first 2048 threads, one uint2 each.
    if (gtid < 64 * 32) {
        int lane  = gtid & 31;
        int tile  = gtid >> 5;
        int kstep = tile >> 3;
        int ntile = tile & 7;
        int tid4  = lane & 3;
        int gid   = lane >> 2;
        int k0 = kstep * 16 + tid4 * 2;
        int n  = ntile * 8 + gid;
        __half2 r0 = __floats2half2_rn(agg_W[n * 128 + k0],     agg_W[n * 128 + k0 + 1]);
        __half2 r1 = __floats2half2_rn(agg_W[n * 128 + k0 + 8], agg_W[n * 128 + k0 + 9]);
        uint2 u;
        u.x = *reinterpret_cast<unsigned int*>(&r0);
        u.y = *reinterpret_cast<unsigned int*>(&r1);
        g_Bfrag[tile * 32 + lane] = u;
    }

    // cate_emb fp16 shadow: one uint4 (8 halfs) per item, v_cates*8 items.
    // Grid has n_rows*16 >= v_cates*8 threads.
    if (gtid < v_cates * 8) {
        const float4* src = (const float4*)cate_emb + (size_t)gtid * 2;
        float4 v0 = __ldg(src);
        float4 v1 = __ldg(src + 1);
        __half2 c0 = __floats2half2_rn(v0.x, v0.y);
        __half2 c1 = __floats2half2_rn(v0.z, v0.w);
        __half2 c2 = __floats2half2_rn(v1.x, v1.y);
        __half2 c3 = __floats2half2_rn(v1.z, v1.w);
        uint4 w;
        w.x = *reinterpret_cast<unsigned int*>(&c0);
        w.y = *reinterpret_cast<unsigned int*>(&c1);
        w.z = *reinterpret_cast<unsigned int*>(&c2);
        w.w = *reinterpret_cast<unsigned int*>(&c3);
        g_ce_h[gtid] = w;
    }

    int row = gtid >> 4;
    int sub = gtid & 15;
    if (row >= n_rows) return;
    int lane = threadIdx.x & 31;
    int group_base = lane & 16;

    int myidx = 0;
    if (sub < NSC) myidx = __ldg(cate_scene_pad + (size_t)row * NSC + sub);

    float4 acc = make_float4(0.f, 0.f, 0.f, 0.f);
#pragma unroll
    for (int k = 0; k < NSC; k++) {
        int j = __shfl_sync(FULL, myidx, group_base + k);
        float4 v = ((const float4*)(scene_emb + (size_t)j * D))[sub];
        acc.x += v.x; acc.y += v.y; acc.z += v.z; acc.w += v.w;
    }

    float sq = acc.x * acc.x + acc.y * acc.y + acc.z * acc.z + acc.w * acc.w;
#pragma unroll
    for (int o = 8; o >= 1; o >>= 1)
        sq += __shfl_xor_sync(FULL, sq, o);

    float scale = sq + EPSF;
    float inv = 1.0f / scale;

    __half2 h0 = __floats2half2_rn(acc.x * inv, acc.y * inv);
    __half2 h1 = __floats2half2_rn(acc.z * inv, acc.w * inv);
    uint2 u;
    u.x = *reinterpret_cast<unsigned int*>(&h0);
    u.y = *reinterpret_cast<unsigned int*>(&h1);
    ((uint2*)g_rs_h)[(size_t)row * 16 + sub] = u;

    if (sub == 0) g_ss[row] = make_float2(scale, sq * inv * inv);
}

// Butterfly merge at xor-offset o.
__device__ __forceinline__ float bmerge(float a, float b, int o, int lane) {
    float x = (lane & o) ? b : a;
    float y = (lane & o) ? a : b;
    y = __shfl_xor_sync(FULL, y, o);
    return x + y;
}

__device__ __forceinline__ void mma16816(float* c, uint32_t a0, uint32_t a1,
                                         uint32_t a2, uint32_t a3,
                                         uint32_t b0, uint32_t b1) {
    asm volatile(
        "mma.sync.aligned.m16n8k16.row.col.f32.f16.f16.f32 "
        "{%0,%1,%2,%3}, {%4,%5,%6,%7}, {%8,%9}, {%0,%1,%2,%3};"
        : "+f"(c[0]), "+f"(c[1]), "+f"(c[2]), "+f"(c[3])
        : "r"(a0), "r"(a1), "r"(a2), "r"(a3), "r"(b0), "r"(b1));
}

// fp16 row (16B/lane) dot fp32 self fragments
__device__ __forceinline__ float dot8(uint4 u, float2 s0, float2 s1,
                                      float2 s2, float2 s3) {
    float2 f0 = h2f(u.x), f1 = h2f(u.y), f2 = h2f(u.z), f3 = h2f(u.w);
    float d = f0.x * s0.x;
    d = fmaf(f0.y, s0.y, d);
    d = fmaf(f1.x, s1.x, d);
    d = fmaf(f1.y, s1.y, d);
    d = fmaf(f2.x, s2.x, d);
    d = fmaf(f2.y, s2.y, d);
    d = fmaf(f3.x, s3.x, d);
    d = fmaf(f3.y, s3.y, d);
    return d;
}

// ---------------------------------------------------------------------------
// Kernel B: each warp owns 16 rows end-to-end.
//   Phase 1: quarter-warp rows — 4 rows/iter, 8 lanes/row, 16B/lane.
//            ALL gathers fp16 (128B rows): dot 1 wf + ce 1 wf per neighbor.
//   Phase 2: 64x HMMA m16n8k16 -> out[16][64] per warp; bias+ELU; direct STG.
// ---------------------------------------------------------------------------
__global__ void __launch_bounds__(256, 4)
main_kernel(const int* __restrict__ c_cate_pad,
            const float* __restrict__ agg_b,
            float* __restrict__ out,
            int n_rows, int v_cates) {
    __shared__ __half sA[RPB * ASTRIDE];   // 128 rows x 136 halfs (pad 8)

    int tid  = threadIdx.x;
    int warp = tid >> 5;
    int lane = tid & 31;

    int rowbase = blockIdx.x * RPB + warp * RPW;
    int q     = lane >> 3;       // quarter = row within group of 4
    int s     = lane & 7;        // lane within quarter
    int qbase = lane & 24;       // shuffle base of this quarter

    // ---- batched neighbor-index prefetch (each lane: neighbors 2s, 2s+1) ----
    int2 nid[4];
#pragma unroll
    for (int rp = 0; rp < 4; rp++) {
        int row  = rowbase + 4 * rp + q;
        int vrow = row < n_rows ? row : n_rows - 1;
        nid[rp] = __ldg((const int2*)(c_cate_pad + (size_t)vrow * NGH) + s);
    }

    // ---- Phase 1: attention, 4 rows per iteration ----
#pragma unroll 1
    for (int rp = 0; rp < 4; rp++) {
        int row  = rowbase + 4 * rp + q;
        int vrow = row < n_rows ? row : n_rows - 1;
        int2 nd = nid[rp];

        uint4 us = __ldg((const uint4*)g_rs_h + (size_t)vrow * 8 + s);
        float2 ss = g_ss[vrow];                 // (scale, selfsim)
        float2 sf0 = h2f(us.x), sf1 = h2f(us.y), sf2 = h2f(us.z), sf3 = h2f(us.w);

        // 16 neighbor dot partials (LDG.128 gathers, 2 per jj)
        float dtp[16];
#pragma unroll
        for (int jj = 0; jj < 8; jj++) {
            int px = __shfl_sync(FULL, nd.x, qbase + jj);
            int py = __shfl_sync(FULL, nd.y, qbase + jj);
            uint4 ux = __ldg((const uint4*)g_rs_h + (size_t)px * 8 + s);
            uint4 uy = __ldg((const uint4*)g_rs_h + (size_t)py * 8 + s);
            dtp[2 * jj]     = dot8(ux, sf0, sf1, sf2, sf3);
            dtp[2 * jj + 1] = dot8(uy, sf0, sf1, sf2, sf3);
        }

        // 8-lane butterfly: lane s ends with dots for neighbors 2s, 2s+1
#pragma unroll
        for (int i = 0; i < 8; i++) dtp[i] = bmerge(dtp[i], dtp[i + 8], 4, lane);
#pragma unroll
        for (int i = 0; i < 4; i++) dtp[i] = bmerge(dtp[i], dtp[i + 4], 2, lane);
#pragma unroll
        for (int i = 0; i < 2; i++) dtp[i] = bmerge(dtp[i], dtp[i + 2], 1, lane);

        float miu0 = (nd.x < v_cates - 1) ? __expf(dtp[0]) : 0.f;
        float miu1 = (nd.y < v_cates - 1) ? __expf(dtp[1]) : 0.f;

        // denom over the quarter
        float dv = miu0 + miu1;
#pragma unroll
        for (int o = 4; o >= 1; o >>= 1)
            dv += __shfl_xor_sync(FULL, dv, o);

        float miu_self = (vrow < v_cates - 1) ? __expf(ss.y) : 0.f;
        float rden = 1.0f / (dv + miu_self + EPSF);

        // aggregation: lane covers e = 8s..8s+7; ce gathers fp16 (1 wf each)
        uint4 cs = __ldg(&g_ce_h[(size_t)vrow * 8 + s]);
        ull msd = pk2(miu_self, miu_self);
        ull A0, A1, A2, A3;
        fma2(A0, msd, h2p(cs.x), pk2(0.f, 0.f));
        fma2(A1, msd, h2p(cs.y), pk2(0.f, 0.f));
        fma2(A2, msd, h2p(cs.z), pk2(0.f, 0.f));
        fma2(A3, msd, h2p(cs.w), pk2(0.f, 0.f));
#pragma unroll
        for (int jj = 0; jj < 8; jj++) {
            float m0 = __shfl_sync(FULL, miu0, qbase + jj);
            float m1 = __shfl_sync(FULL, miu1, qbase + jj);
            int   px = __shfl_sync(FULL, nd.x, qbase + jj);
            int   py = __shfl_sync(FULL, nd.y, qbase + jj);
            uint4 cu = __ldg(&g_ce_h[(size_t)px * 8 + s]);
            uint4 cw = __ldg(&g_ce_h[(size_t)py * 8 + s]);
            ull mm0 = pk2(m0, m0);
            ull mm1 = pk2(m1, m1);
            fma2(A0, mm0, h2p(cu.x), A0);
            fma2(A1, mm0, h2p(cu.y), A1);
            fma2(A2, mm0, h2p(cu.z), A2);
            fma2(A3, mm0, h2p(cu.w), A3);
            fma2(A0, mm1, h2p(cw.x), A0);
            fma2(A1, mm1, h2p(cw.y), A1);
            fma2(A2, mm1, h2p(cw.z), A2);
            fma2(A3, mm1, h2p(cw.w), A3);
        }
        float2 g0 = upk2(A0), g1 = upk2(A1), g2 = upk2(A2), g3 = upk2(A3);

        // h store (fp16): rs at e=8s.., agg at e=64+8s.. — STS.128, conflict-free
        int rt = warp * RPW + 4 * rp + q;
        __half* hrow = sA + rt * ASTRIDE;
        float sc = ss.x;
        __half2 r0 = __floats2half2_rn(sf0.x * sc, sf0.y * sc);
        __half2 r1 = __floats2half2_rn(sf1.x * sc, sf1.y * sc);
        __half2 r2 = __floats2half2_rn(sf2.x * sc, sf2.y * sc);
        __half2 r3 = __floats2half2_rn(sf3.x * sc, sf3.y * sc);
        uint4 w0;
        w0.x = *reinterpret_cast<unsigned int*>(&r0);
        w0.y = *reinterpret_cast<unsigned int*>(&r1);
        w0.z = *reinterpret_cast<unsigned int*>(&r2);
        w0.w = *reinterpret_cast<unsigned int*>(&r3);
        *(uint4*)(hrow + 8 * s) = w0;

        __half2 a0 = __floats2half2_rn(g0.x * rden, g0.y * rden);
        __half2 a1 = __floats2half2_rn(g1.x * rden, g1.y * rden);
        __half2 a2 = __floats2half2_rn(g2.x * rden, g2.y * rden);
        __half2 a3 = __floats2half2_rn(g3.x * rden, g3.y * rden);
        uint4 w1;
        w1.x = *reinterpret_cast<unsigned int*>(&a0);
        w1.y = *reinterpret_cast<unsigned int*>(&a1);
        w1.z = *reinterpret_cast<unsigned int*>(&a2);
        w1.w = *reinterpret_cast<unsigned int*>(&a3);
        *(uint4*)(hrow + 64 + 8 * s) = w1;
    }
    __syncwarp();

    // ---- Phase 2: HMMA matvec, 16 rows x 64 cols per warp ----
    int gid  = lane >> 2;      // 0..7
    int tid4 = lane & 3;       // 0..3

    float acc[8][4];
#pragma unroll
    for (int n = 0; n < 8; n++)
#pragma unroll
        for (int i = 0; i < 4; i++) acc[n][i] = 0.f;

    const __half* a_base0 = sA + (warp * RPW + gid) * ASTRIDE + tid4 * 2;
    const __half* a_base1 = a_base0 + 8 * ASTRIDE;

#pragma unroll
    for (int k = 0; k < 8; k++) {
        uint32_t a0 = *(const uint32_t*)(a_base0 + k * 16);
        uint32_t a1 = *(const uint32_t*)(a_base1 + k * 16);
        uint32_t a2 = *(const uint32_t*)(a_base0 + k * 16 + 8);
        uint32_t a3 = *(const uint32_t*)(a_base1 + k * 16 + 8);
#pragma unroll
        for (int n = 0; n < 8; n++) {
            uint2 bf = __ldg(&g_Bfrag[(k * 8 + n) * 32 + lane]);
            mma16816(acc[n], a0, a1, a2, a3, bf.x, bf.y);
        }
    }

    // ---- epilogue: bias + ELU + direct stores ----
    int grow0 = rowbase + gid;
    int grow1 = grow0 + 8;
#pragma unroll
    for (int n = 0; n < 8; n++) {
        int col = n * 8 + tid4 * 2;
        float2 bb = *(const float2*)(agg_b + col);
        if (grow0 < n_rows) {
            float v0 = acc[n][0] + bb.x;
            float v1 = acc[n][1] + bb.y;
            v0 = v0 > 0.f ? v0 : expm1f(v0);
            v1 = v1 > 0.f ? v1 : expm1f(v1);
            *(float2*)(out + (size_t)grow0 * D + col) = make_float2(v0, v1);
        }
        if (grow1 < n_rows) {
            float v2 = acc[n][2] + bb.x;
            float v3 = acc[n][3] + bb.y;
            v2 = v2 > 0.f ? v2 : expm1f(v2);
            v3 = v3 > 0.f ? v3 : expm1f(v3);
            *(float2*)(out + (size_t)grow1 * D + col) = make_float2(v2, v3);
        }
    }
}

// ---------------------------------------------------------------------------
// Inputs (metadata order):
//  0 cids, 1 cate_emb_w [Vc,64], 2 scene_emb_w [Vs,64], 3 cate_scene_pad [N,10],
//  4 c_cate_pad [N,16], 5 agg_W [64,128], 6 agg_b [64]   -> out f32 [N,64]
// ---------------------------------------------------------------------------
extern "C" void kernel_launch(void* const* d_in, const int* in_sizes, int n_in,
                              void* d_out, int out_size) {
    const float* cate_emb       = (const float*)d_in[1];
    const float* scene_emb      = (const float*)d_in[2];
    const int*   cate_scene_pad = (const int*)d_in[3];
    const int*   c_cate_pad     = (const int*)d_in[4];
    const float* agg_W          = (const float*)d_in[5];
    const float* agg_b          = (const float*)d_in[6];
    float* out = (float*)d_out;

    int n_rows  = in_sizes[4] / NGH;   // 100000
    int v_cates = in_sizes[1] / D;     // 100000

    int threadsA = 256;
    int blocksA = (n_rows * 16 + threadsA - 1) / threadsA;
    rowsum_kernel<<<blocksA, threadsA>>>(scene_emb, cate_scene_pad, agg_W,
                                         cate_emb, n_rows, v_cates);

    int blocksB = (n_rows + RPB - 1) / RPB;
    main_kernel<<<blocksB, 256>>>(c_cate_pad, agg_b, out, n_rows, v_cates);
}

// round 17
// speedup vs baseline: 1.2314x; 1.0661x over previous
#include <cuda_runtime.h>
#include <cuda_fp16.h>
#include <math.h>
#include <stdint.h>

#define N_ROWS_MAX 100000
#define D 64
#define NGH 16
#define NSC 10
#define EPSF 1e-10f
#define FULL 0xFFFFFFFFu

#define WPB 8           // warps per block
#define RPW 8           // rows per warp (phase 1)
#define RPB 64          // rows per block

#define ASTRIDE 136     // A-tile row stride in halfs (272B) — conflict-free

typedef unsigned long long ull;

// ---- scratch (device globals per allocation rules) ----
__device__ __half2 g_rs_h[(size_t)N_ROWS_MAX * 32];  // rs/(||rs||^2+eps) fp16
__device__ uint4   g_ce_h[(size_t)N_ROWS_MAX * 8];   // cate_emb fp16 shadow (128B/row)
__device__ float2  g_ss[N_ROWS_MAX];                 // (scale = sq+eps, selfsim)
__device__ uint2   g_Bfrag[64 * 32];                 // [kstep*8+ntile][lane]

// ---- packed f32x2 helpers ----
__device__ __forceinline__ ull pk2(float x, float y) {
    ull r; asm("mov.b64 %0, {%1, %2};" : "=l"(r) : "f"(x), "f"(y)); return r;
}
__device__ __forceinline__ float2 upk2(ull v) {
    float2 r; asm("mov.b64 {%0, %1}, %2;" : "=f"(r.x), "=f"(r.y) : "l"(v)); return r;
}
__device__ __forceinline__ void fma2(ull& d, ull a, ull b, ull c) {
    asm("fma.rn.f32x2 %0, %1, %2, %3;" : "=l"(d) : "l"(a), "l"(b), "l"(c));
}
__device__ __forceinline__ float2 h2f(unsigned int h) {
    return __half22float2(*reinterpret_cast<__half2*>(&h));
}
__device__ __forceinline__ ull h2p(unsigned int h) {
    float2 f = h2f(h);
    return pk2(f.x, f.y);
}

// ---------------------------------------------------------------------------
// Kernel A: per-row scene sums -> fp16 normalized table + (scale, selfsim);
// builds HMMA B fragments of agg_W and the fp16 cate_emb shadow.
// ---------------------------------------------------------------------------
__global__ void rowsum_kernel(const float* __restrict__ scene_emb,
                              const int* __restrict__ cate_scene_pad,
                              const float* __restrict__ agg_W,
                              const float* __restrict__ cate_emb,
                              int n_rows, int v_cates) {
    int gtid = blockIdx.x * blockDim.x + threadIdx.x;

    // B-fragment build: first 2048 threads, one uint2 each.
    if (gtid < 64 * 32) {
        int lane  = gtid & 31;
        int tile  = gtid >> 5;
        int kstep = tile >> 3;
        int ntile = tile & 7;
        int tid4  = lane & 3;
        int gid   = lane >> 2;
        int k0 = kstep * 16 + tid4 * 2;
        int n  = ntile * 8 + gid;
        __half2 r0 = __floats2half2_rn(agg_W[n * 128 + k0],     agg_W[n * 128 + k0 + 1]);
        __half2 r1 = __floats2half2_rn(agg_W[n * 128 + k0 + 8], agg_W[n * 128 + k0 + 9]);
        uint2 u;
        u.x = *reinterpret_cast<unsigned int*>(&r0);
        u.y = *reinterpret_cast<unsigned int*>(&r1);
        g_Bfrag[tile * 32 + lane] = u;
    }

    // cate_emb fp16 shadow: one uint4 (8 halfs) per item, v_cates*8 items.
    if (gtid < v_cates * 8) {
        const float4* src = (const float4*)cate_emb + (size_t)gtid * 2;
        float4 v0 = __ldg(src);
        float4 v1 = __ldg(src + 1);
        __half2 c0 = __floats2half2_rn(v0.x, v0.y);
        __half2 c1 = __floats2half2_rn(v0.z, v0.w);
        __half2 c2 = __floats2half2_rn(v1.x, v1.y);
        __half2 c3 = __floats2half2_rn(v1.z, v1.w);
        uint4 w;
        w.x = *reinterpret_cast<unsigned int*>(&c0);
        w.y = *reinterpret_cast<unsigned int*>(&c1);
        w.z = *reinterpret_cast<unsigned int*>(&c2);
        w.w = *reinterpret_cast<unsigned int*>(&c3);
        g_ce_h[gtid] = w;
    }

    int row = gtid >> 4;
    int sub = gtid & 15;
    if (row >= n_rows) return;
    int lane = threadIdx.x & 31;
    int group_base = lane & 16;

    int myidx = 0;
    if (sub < NSC) myidx = __ldg(cate_scene_pad + (size_t)row * NSC + sub);

    float4 acc = make_float4(0.f, 0.f, 0.f, 0.f);
#pragma unroll
    for (int k = 0; k < NSC; k++) {
        int j = __shfl_sync(FULL, myidx, group_base + k);
        float4 v = ((const float4*)(scene_emb + (size_t)j * D))[sub];
        acc.x += v.x; acc.y += v.y; acc.z += v.z; acc.w += v.w;
    }

    float sq = acc.x * acc.x + acc.y * acc.y + acc.z * acc.z + acc.w * acc.w;
#pragma unroll
    for (int o = 8; o >= 1; o >>= 1)
        sq += __shfl_xor_sync(FULL, sq, o);

    float scale = sq + EPSF;
    float inv = 1.0f / scale;

    __half2 h0 = __floats2half2_rn(acc.x * inv, acc.y * inv);
    __half2 h1 = __floats2half2_rn(acc.z * inv, acc.w * inv);
    uint2 u;
    u.x = *reinterpret_cast<unsigned int*>(&h0);
    u.y = *reinterpret_cast<unsigned int*>(&h1);
    ((uint2*)g_rs_h)[(size_t)row * 16 + sub] = u;

    if (sub == 0) g_ss[row] = make_float2(scale, sq * inv * inv);
}

// Butterfly merge at xor-offset o.
__device__ __forceinline__ float bmerge(float a, float b, int o, int lane) {
    float x = (lane & o) ? b : a;
    float y = (lane & o) ? a : b;
    y = __shfl_xor_sync(FULL, y, o);
    return x + y;
}

__device__ __forceinline__ void mma16816(float* c, uint32_t a0, uint32_t a1,
                                         uint32_t a2, uint32_t a3,
                                         uint32_t b0, uint32_t b1) {
    asm volatile(
        "mma.sync.aligned.m16n8k16.row.col.f32.f16.f16.f32 "
        "{%0,%1,%2,%3}, {%4,%5,%6,%7}, {%8,%9}, {%0,%1,%2,%3};"
        : "+f"(c[0]), "+f"(c[1]), "+f"(c[2]), "+f"(c[3])
        : "r"(a0), "r"(a1), "r"(a2), "r"(a3), "r"(b0), "r"(b1));
}

// fp16 row (16B/lane) dot fp32 self fragments
__device__ __forceinline__ float dot8(uint4 u, float2 s0, float2 s1,
                                      float2 s2, float2 s3) {
    float2 f0 = h2f(u.x), f1 = h2f(u.y), f2 = h2f(u.z), f3 = h2f(u.w);
    float d = f0.x * s0.x;
    d = fmaf(f0.y, s0.y, d);
    d = fmaf(f1.x, s1.x, d);
    d = fmaf(f1.y, s1.y, d);
    d = fmaf(f2.x, s2.x, d);
    d = fmaf(f2.y, s2.y, d);
    d = fmaf(f3.x, s3.x, d);
    d = fmaf(f3.y, s3.y, d);
    return d;
}

// ---------------------------------------------------------------------------
// Kernel B: 64 rows per block (finer grid -> less wave-quantization waste).
//   Phase 1: each warp owns 8 rows — quarter-warp form, 2 iterations.
//   Phase 2 (cross-warp after __syncthreads): warp w does the 16-row HMMA
//            for row-group (w>>1) over n-column half (w&1): 4 n-tiles,
//            acc[4][4].
// ---------------------------------------------------------------------------
__global__ void __launch_bounds__(256, 4)
main_kernel(const int* __restrict__ c_cate_pad,
            const float* __restrict__ agg_b,
            float* __restrict__ out,
            int n_rows, int v_cates) {
    __shared__ __half sA[RPB * ASTRIDE];   // 64 rows x 136 halfs (pad 8)

    int tid  = threadIdx.x;
    int warp = tid >> 5;
    int lane = tid & 31;

    int blockrow = blockIdx.x * RPB;
    int rowbase  = blockrow + warp * RPW;
    int q     = lane >> 3;       // row within group of 4
    int s     = lane & 7;        // lane within quarter
    int qbase = lane & 24;       // shuffle base of this quarter

    // ---- batched neighbor-index prefetch (each lane: neighbors 2s, 2s+1) ----
    int2 nid[RPW / 4];
#pragma unroll
    for (int rp = 0; rp < RPW / 4; rp++) {
        int row  = rowbase + 4 * rp + q;
        int vrow = row < n_rows ? row : n_rows - 1;
        nid[rp] = __ldg((const int2*)(c_cate_pad + (size_t)vrow * NGH) + s);
    }

    // ---- Phase 1: attention, 4 rows per iteration ----
#pragma unroll 1
    for (int rp = 0; rp < RPW / 4; rp++) {
        int row  = rowbase + 4 * rp + q;
        int vrow = row < n_rows ? row : n_rows - 1;
        int2 nd = nid[rp];

        uint4 us = __ldg((const uint4*)g_rs_h + (size_t)vrow * 8 + s);
        float2 ss = g_ss[vrow];                 // (scale, selfsim)
        float2 sf0 = h2f(us.x), sf1 = h2f(us.y), sf2 = h2f(us.z), sf3 = h2f(us.w);

        // 16 neighbor dot partials (LDG.128 gathers, 2 per jj)
        float dtp[16];
#pragma unroll
        for (int jj = 0; jj < 8; jj++) {
            int px = __shfl_sync(FULL, nd.x, qbase + jj);
            int py = __shfl_sync(FULL, nd.y, qbase + jj);
            uint4 ux = __ldg((const uint4*)g_rs_h + (size_t)px * 8 + s);
            uint4 uy = __ldg((const uint4*)g_rs_h + (size_t)py * 8 + s);
            dtp[2 * jj]     = dot8(ux, sf0, sf1, sf2, sf3);
            dtp[2 * jj + 1] = dot8(uy, sf0, sf1, sf2, sf3);
        }

        // 8-lane butterfly: lane s ends with dots for neighbors 2s, 2s+1
#pragma unroll
        for (int i = 0; i < 8; i++) dtp[i] = bmerge(dtp[i], dtp[i + 8], 4, lane);
#pragma unroll
        for (int i = 0; i < 4; i++) dtp[i] = bmerge(dtp[i], dtp[i + 4], 2, lane);
#pragma unroll
        for (int i = 0; i < 2; i++) dtp[i] = bmerge(dtp[i], dtp[i + 2], 1, lane);

        float miu0 = (nd.x < v_cates - 1) ? __expf(dtp[0]) : 0.f;
        float miu1 = (nd.y < v_cates - 1) ? __expf(dtp[1]) : 0.f;

        // denom over the quarter
        float dv = miu0 + miu1;
#pragma unroll
        for (int o = 4; o >= 1; o >>= 1)
            dv += __shfl_xor_sync(FULL, dv, o);

        float miu_self = (vrow < v_cates - 1) ? __expf(ss.y) : 0.f;
        float rden = 1.0f / (dv + miu_self + EPSF);

        // aggregation: lane covers e = 8s..8s+7; ce gathers fp16 (1 wf each)
        uint4 cs = __ldg(&g_ce_h[(size_t)vrow * 8 + s]);
        ull msd = pk2(miu_self, miu_self);
        ull A0, A1, A2, A3;
        fma2(A0, msd, h2p(cs.x), pk2(0.f, 0.f));
        fma2(A1, msd, h2p(cs.y), pk2(0.f, 0.f));
        fma2(A2, msd, h2p(cs.z), pk2(0.f, 0.f));
        fma2(A3, msd, h2p(cs.w), pk2(0.f, 0.f));
#pragma unroll
        for (int jj = 0; jj < 8; jj++) {
            float m0 = __shfl_sync(FULL, miu0, qbase + jj);
            float m1 = __shfl_sync(FULL, miu1, qbase + jj);
            int   px = __shfl_sync(FULL, nd.x, qbase + jj);
            int   py = __shfl_sync(FULL, nd.y, qbase + jj);
            uint4 cu = __ldg(&g_ce_h[(size_t)px * 8 + s]);
            uint4 cw = __ldg(&g_ce_h[(size_t)py * 8 + s]);
            ull mm0 = pk2(m0, m0);
            ull mm1 = pk2(m1, m1);
            fma2(A0, mm0, h2p(cu.x), A0);
            fma2(A1, mm0, h2p(cu.y), A1);
            fma2(A2, mm0, h2p(cu.z), A2);
            fma2(A3, mm0, h2p(cu.w), A3);
            fma2(A0, mm1, h2p(cw.x), A0);
            fma2(A1, mm1, h2p(cw.y), A1);
            fma2(A2, mm1, h2p(cw.z), A2);
            fma2(A3, mm1, h2p(cw.w), A3);
        }
        float2 g0 = upk2(A0), g1 = upk2(A1), g2 = upk2(A2), g3 = upk2(A3);

        // h store (fp16): rs at e=8s.., agg at e=64+8s.. — STS.128, conflict-free
        int rt = warp * RPW + 4 * rp + q;
        __half* hrow = sA + rt * ASTRIDE;
        float sc = ss.x;
        __half2 r0 = __floats2half2_rn(sf0.x * sc, sf0.y * sc);
        __half2 r1 = __floats2half2_rn(sf1.x * sc, sf1.y * sc);
        __half2 r2 = __floats2half2_rn(sf2.x * sc, sf2.y * sc);
        __half2 r3 = __floats2half2_rn(sf3.x * sc, sf3.y * sc);
        uint4 w0;
        w0.x = *reinterpret_cast<unsigned int*>(&r0);
        w0.y = *reinterpret_cast<unsigned int*>(&r1);
        w0.z = *reinterpret_cast<unsigned int*>(&r2);
        w0.w = *reinterpret_cast<unsigned int*>(&r3);
        *(uint4*)(hrow + 8 * s) = w0;

        __half2 a0 = __floats2half2_rn(g0.x * rden, g0.y * rden);
        __half2 a1 = __floats2half2_rn(g1.x * rden, g1.y * rden);
        __half2 a2 = __floats2half2_rn(g2.x * rden, g2.y * rden);
        __half2 a3 = __floats2half2_rn(g3.x * rden, g3.y * rden);
        uint4 w1;
        w1.x = *reinterpret_cast<unsigned int*>(&a0);
        w1.y = *reinterpret_cast<unsigned int*>(&a1);
        w1.z = *reinterpret_cast<unsigned int*>(&a2);
        w1.w = *reinterpret_cast<unsigned int*>(&a3);
        *(uint4*)(hrow + 64 + 8 * s) = w1;
    }
    __syncthreads();

    // ---- Phase 2 (cross-warp): warp w -> row-group (w>>1), n-half (w&1) ----
    int gid  = lane >> 2;      // 0..7
    int tid4 = lane & 3;       // 0..3
    int rg   = warp >> 1;      // 0..3 (16-row group within 64-row tile)
    int nh   = warp & 1;       // 0..1 (column half)

    float acc[4][4];
#pragma unroll
    for (int n = 0; n < 4; n++)
#pragma unroll
        for (int i = 0; i < 4; i++) acc[n][i] = 0.f;

    const __half* a_base0 = sA + (rg * 16 + gid) * ASTRIDE + tid4 * 2;
    const __half* a_base1 = a_base0 + 8 * ASTRIDE;

#pragma unroll
    for (int k = 0; k < 8; k++) {
        uint32_t a0 = *(const uint32_t*)(a_base0 + k * 16);
        uint32_t a1 = *(const uint32_t*)(a_base1 + k * 16);
        uint32_t a2 = *(const uint32_t*)(a_base0 + k * 16 + 8);
        uint32_t a3 = *(const uint32_t*)(a_base1 + k * 16 + 8);
#pragma unroll
        for (int n = 0; n < 4; n++) {
            uint2 bf = __ldg(&g_Bfrag[(k * 8 + nh * 4 + n) * 32 + lane]);
            mma16816(acc[n], a0, a1, a2, a3, bf.x, bf.y);
        }
    }

    // ---- epilogue: bias + ELU + direct stores ----
    int grow0 = blockrow + rg * 16 + gid;
    int grow1 = grow0 + 8;
#pragma unroll
    for (int n = 0; n < 4; n++) {
        int col = (nh * 4 + n) * 8 + tid4 * 2;
        float2 bb = *(const float2*)(agg_b + col);
        if (grow0 < n_rows) {
            float v0 = acc[n][0] + bb.x;
            float v1 = acc[n][1] + bb.y;
            v0 = v0 > 0.f ? v0 : expm1f(v0);
            v1 = v1 > 0.f ? v1 : expm1f(v1);
            *(float2*)(out + (size_t)grow0 * D + col) = make_float2(v0, v1);
        }
        if (grow1 < n_rows) {
            float v2 = acc[n][2] + bb.x;
            float v3 = acc[n][3] + bb.y;
            v2 = v2 > 0.f ? v2 : expm1f(v2);
            v3 = v3 > 0.f ? v3 : expm1f(v3);
            *(float2*)(out + (size_t)grow1 * D + col) = make_float2(v2, v3);
        }
    }
}

// ---------------------------------------------------------------------------
// Inputs (metadata order):
//  0 cids, 1 cate_emb_w [Vc,64], 2 scene_emb_w [Vs,64], 3 cate_scene_pad [N,10],
//  4 c_cate_pad [N,16], 5 agg_W [64,128], 6 agg_b [64]   -> out f32 [N,64]
// ---------------------------------------------------------------------------
extern "C" void kernel_launch(void* const* d_in, const int* in_sizes, int n_in,
                              void* d_out, int out_size) {
    const float* cate_emb       = (const float*)d_in[1];
    const float* scene_emb      = (const float*)d_in[2];
    const int*   cate_scene_pad = (const int*)d_in[3];
    const int*   c_cate_pad     = (const int*)d_in[4];
    const float* agg_W          = (const float*)d_in[5];
    const float* agg_b          = (const float*)d_in[6];
    float* out = (float*)d_out;

    int n_rows  = in_sizes[4] / NGH;   // 100000
    int v_cates = in_sizes[1] / D;     // 100000

    int threadsA = 256;
    int blocksA = (n_rows * 16 + threadsA - 1) / threadsA;
    rowsum_kernel<<<blocksA, threadsA>>>(scene_emb, cate_scene_pad, agg_W,
                                         cate_emb, n_rows, v_cates);

    int blocksB = (n_rows + RPB - 1) / RPB;
    main_kernel<<<blocksB, 256>>>(c_cate_pad, agg_b, out, n_rows, v_cates);
}